// round 1
// baseline (speedup 1.0000x reference)
#include <cuda_runtime.h>
#include <math.h>

#define LSEQ 4096
#define BATCH 4
#define KDIM 128
#define DDIM 512
#define QT 64
#define ST 64
#define INV_TAU 30.0f
#define QPAD 132
#define PPAD 68

// Scratch: projected tensors, [B][L][·] layout so the attention kernel reads
// contiguous per-batch rows. Static __device__ globals (no allocation allowed).
__device__ float g_wq[BATCH * LSEQ * KDIM];   // 8 MB
__device__ float g_wk[BATCH * LSEQ * KDIM];   // 8 MB
__device__ float g_wv[BATCH * LSEQ * DDIM];   // 32 MB

// ---------------------------------------------------------------------------
// Projection kernel: out[bi][li][n0+n] = X[m][:] . W[n0+n][:] + bias[n0+n]
// X: [L*B][512] row-major ([L][B][D] flattened). W: [Ntot][512] row-major.
// Block: 128 threads, 16 rows x 128 cols. Optional fused L2-normalize
// (doNorm=1 requires Ntot==128 so the block covers the full output row).
// ---------------------------------------------------------------------------
__global__ __launch_bounds__(128) void proj_kernel(
    const float* __restrict__ X, const float* __restrict__ W,
    const float* __restrict__ bias, float* __restrict__ out,
    int Ntot, int doNorm)
{
    __shared__ float xs[16][32];       // X chunk, broadcast reads
    __shared__ float ws[128][36];      // W chunk, padded: conflict-free LDS.128
    __shared__ float outs[16][128];    // staging for l2norm reduction

    const int tid = threadIdx.x;
    const int m0 = blockIdx.x * 16;
    const int n0 = blockIdx.y * 128;

    float acc[16];
#pragma unroll
    for (int r = 0; r < 16; r++) acc[r] = 0.f;

    for (int ck = 0; ck < 16; ck++) {
        __syncthreads();
        {   // load X tile [16][32]: 128 float4, one per thread, coalesced
            int row = tid >> 3, c4 = tid & 7;
            *(float4*)&xs[row][c4 * 4] =
                *(const float4*)(X + (size_t)(m0 + row) * 512 + ck * 32 + c4 * 4);
        }
#pragma unroll
        for (int i = 0; i < 8; i++) {   // load W tile [128][32]: 1024 float4
            int f = tid + 128 * i;
            int row = f >> 3, c4 = f & 7;
            *(float4*)&ws[row][c4 * 4] =
                *(const float4*)(W + (size_t)(n0 + row) * 512 + ck * 32 + c4 * 4);
        }
        __syncthreads();
#pragma unroll
        for (int d4 = 0; d4 < 8; d4++) {
            float4 w4 = *(float4*)&ws[tid][d4 * 4];
#pragma unroll
            for (int r = 0; r < 16; r++) {
                float4 x4 = *(float4*)&xs[r][d4 * 4];
                acc[r] += x4.x * w4.x + x4.y * w4.y + x4.z * w4.z + x4.w * w4.w;
            }
        }
    }

    float bv = bias[n0 + tid];
    if (!doNorm) {
#pragma unroll
        for (int r = 0; r < 16; r++) {
            int m = m0 + r;
            int li = m >> 2, bi = m & 3;
            out[(size_t)bi * LSEQ * Ntot + (size_t)li * Ntot + n0 + tid] = acc[r] + bv;
        }
    } else {
#pragma unroll
        for (int r = 0; r < 16; r++) outs[r][tid] = acc[r] + bv;
        __syncthreads();
        int w = tid >> 5, lane = tid & 31;
#pragma unroll
        for (int r = 0; r < 4; r++) {
            int row = w * 4 + r;
            float4 v = *(float4*)&outs[row][lane * 4];
            float ss = v.x * v.x + v.y * v.y + v.z * v.z + v.w * v.w;
#pragma unroll
            for (int o = 16; o >= 1; o >>= 1)
                ss += __shfl_xor_sync(0xffffffffu, ss, o);
            float sc = 1.f / fmaxf(sqrtf(ss), 1e-12f);
            int m = m0 + row;
            int li = m >> 2, bi = m & 3;
            float4 o4 = make_float4(v.x * sc, v.y * sc, v.z * sc, v.w * sc);
            *(float4*)(out + (size_t)bi * LSEQ * Ntot + (size_t)li * Ntot + lane * 4) = o4;
        }
    }
}

// ---------------------------------------------------------------------------
// Flash attention, fp32 SIMT. Block = 256 threads, QT=64 q rows, full D=512.
// Thread layout: tq = tid>>4 owns q rows {4tq..4tq+3} in BOTH phases so the
// online-softmax state (m, l, alpha) stays thread-local.
//   QK phase: tc = tid&15 owns s cols {tc, tc+16, tc+32, tc+48} (strided ->
//             conflict-free padded K reads).
//   PV phase: tc owns d cols {tc*4 + 64*j + c} (coalesced V float4 reads).
// O accumulators: 4 rows x 8 float4 = 128 fp32 registers per thread.
// ---------------------------------------------------------------------------
__global__ __launch_bounds__(256, 1) void flash_kernel(
    const float* __restrict__ wq, const float* __restrict__ wk,
    const float* __restrict__ wv, float* __restrict__ out)
{
    extern __shared__ float sm[];
    float* qs = sm;                     // [64][QPAD]
    float* ks = sm + QT * QPAD;         // [64][QPAD]
    float* ps = sm + 2 * QT * QPAD;     // [64][PPAD]

    const int tid = threadIdx.x;
    const int b = blockIdx.y;
    const int q0 = blockIdx.x * QT;
    const int tq = tid >> 4;
    const int tc = tid & 15;

    const float* wq_b = wq + (size_t)b * LSEQ * KDIM;
    const float* wk_b = wk + (size_t)b * LSEQ * KDIM;
    const float* wv_b = wv + (size_t)b * LSEQ * DDIM;

    // load Q tile (stays resident all kernel)
    for (int f = tid; f < QT * KDIM / 4; f += 256) {
        int row = f >> 5, c4 = f & 31;
        *(float4*)(qs + row * QPAD + c4 * 4) =
            *(const float4*)(wq_b + (size_t)(q0 + row) * KDIM + c4 * 4);
    }

    float mI[4], lI[4];
    float4 O[4][8];
#pragma unroll
    for (int r = 0; r < 4; r++) {
        mI[r] = -1e30f;
        lI[r] = 0.f;
#pragma unroll
        for (int j = 0; j < 8; j++) O[r][j] = make_float4(0.f, 0.f, 0.f, 0.f);
    }

    for (int st = 0; st < LSEQ / ST; st++) {
        __syncthreads();
        for (int f = tid; f < ST * KDIM / 4; f += 256) {
            int row = f >> 5, c4 = f & 31;
            *(float4*)(ks + row * QPAD + c4 * 4) =
                *(const float4*)(wk_b + (size_t)(st * ST + row) * KDIM + c4 * 4);
        }
        __syncthreads();

        // ---- S = Q . K^T  (4x4 register tile per thread) ----
        float sacc[4][4];
#pragma unroll
        for (int r = 0; r < 4; r++)
#pragma unroll
            for (int c = 0; c < 4; c++) sacc[r][c] = 0.f;

#pragma unroll 4
        for (int k4 = 0; k4 < 32; k4++) {
            float4 kv[4];
#pragma unroll
            for (int c = 0; c < 4; c++)
                kv[c] = *(float4*)(ks + (tc + 16 * c) * QPAD + k4 * 4);
#pragma unroll
            for (int r = 0; r < 4; r++) {
                float4 q4 = *(float4*)(qs + (4 * tq + r) * QPAD + k4 * 4);
#pragma unroll
                for (int c = 0; c < 4; c++) {
                    sacc[r][c] += q4.x * kv[c].x + q4.y * kv[c].y
                                + q4.z * kv[c].z + q4.w * kv[c].w;
                }
            }
        }

        // ---- online softmax (rows reduced across the 16-lane tc group) ----
        float alpha[4];
#pragma unroll
        for (int r = 0; r < 4; r++) {
            float s0 = sacc[r][0] * INV_TAU;
            float s1 = sacc[r][1] * INV_TAU;
            float s2 = sacc[r][2] * INV_TAU;
            float s3 = sacc[r][3] * INV_TAU;
            float mx = fmaxf(fmaxf(s0, s1), fmaxf(s2, s3));
#pragma unroll
            for (int o = 8; o >= 1; o >>= 1)
                mx = fmaxf(mx, __shfl_xor_sync(0xffffffffu, mx, o));
            float mn = fmaxf(mI[r], mx);
            float p0 = __expf(s0 - mn);
            float p1 = __expf(s1 - mn);
            float p2 = __expf(s2 - mn);
            float p3 = __expf(s3 - mn);
            float sum = p0 + p1 + p2 + p3;
#pragma unroll
            for (int o = 8; o >= 1; o >>= 1)
                sum += __shfl_xor_sync(0xffffffffu, sum, o);
            alpha[r] = __expf(mI[r] - mn);
            lI[r] = lI[r] * alpha[r] + sum;
            mI[r] = mn;
            int prow = (4 * tq + r) * PPAD;
            ps[prow + tc]      = p0;
            ps[prow + tc + 16] = p1;
            ps[prow + tc + 32] = p2;
            ps[prow + tc + 48] = p3;
        }
        __syncwarp();   // ps rows are produced/consumed within one warp

        // ---- rescale O, then O += P . V ----
#pragma unroll
        for (int r = 0; r < 4; r++) {
            float a = alpha[r];
#pragma unroll
            for (int j = 0; j < 8; j++) {
                O[r][j].x *= a; O[r][j].y *= a; O[r][j].z *= a; O[r][j].w *= a;
            }
        }

        const float* vb = wv_b + (size_t)(st * ST) * DDIM + tc * 4;
#pragma unroll 2
        for (int s = 0; s < ST; s++) {
            float p0 = ps[(4 * tq + 0) * PPAD + s];
            float p1 = ps[(4 * tq + 1) * PPAD + s];
            float p2 = ps[(4 * tq + 2) * PPAD + s];
            float p3 = ps[(4 * tq + 3) * PPAD + s];
            const float* vrow = vb + (size_t)s * DDIM;
#pragma unroll
            for (int j = 0; j < 8; j++) {
                float4 v = *(const float4*)(vrow + 64 * j);
                O[0][j].x += p0 * v.x; O[0][j].y += p0 * v.y;
                O[0][j].z += p0 * v.z; O[0][j].w += p0 * v.w;
                O[1][j].x += p1 * v.x; O[1][j].y += p1 * v.y;
                O[1][j].z += p1 * v.z; O[1][j].w += p1 * v.w;
                O[2][j].x += p2 * v.x; O[2][j].y += p2 * v.y;
                O[2][j].z += p2 * v.z; O[2][j].w += p2 * v.w;
                O[3][j].x += p3 * v.x; O[3][j].y += p3 * v.y;
                O[3][j].z += p3 * v.z; O[3][j].w += p3 * v.w;
            }
        }
    }

    // ---- epilogue: normalize by l, write [L][B][D] ----
#pragma unroll
    for (int r = 0; r < 4; r++) {
        float inv = 1.f / lI[r];
        int row = q0 + 4 * tq + r;
        float* orow = out + (size_t)row * BATCH * DDIM + (size_t)b * DDIM + tc * 4;
#pragma unroll
        for (int j = 0; j < 8; j++) {
            float4 o = O[r][j];
            o.x *= inv; o.y *= inv; o.z *= inv; o.w *= inv;
            *(float4*)(orow + 64 * j) = o;
        }
    }
}

// ---------------------------------------------------------------------------
extern "C" void kernel_launch(void* const* d_in, const int* in_sizes, int n_in,
                              void* d_out, int out_size)
{
    const float* query = (const float*)d_in[0];
    const float* key   = (const float*)d_in[1];
    const float* value = (const float*)d_in[2];
    const float* WKw   = (const float*)d_in[3];
    const float* WKb   = (const float*)d_in[4];
    const float* WVw   = (const float*)d_in[5];
    const float* WVb   = (const float*)d_in[6];
    float* out = (float*)d_out;
    (void)in_sizes; (void)n_in; (void)out_size;

    void *pq, *pk, *pv;
    cudaGetSymbolAddress(&pq, g_wq);
    cudaGetSymbolAddress(&pk, g_wk);
    cudaGetSymbolAddress(&pv, g_wv);

    int smem = (2 * QT * QPAD + QT * PPAD) * (int)sizeof(float);  // ~85 KB
    cudaFuncSetAttribute(flash_kernel,
                         cudaFuncAttributeMaxDynamicSharedMemorySize, smem);

    dim3 gk(LSEQ * BATCH / 16, 1);
    proj_kernel<<<gk, 128>>>(query, WKw, WKb, (float*)pq, KDIM, 1);
    proj_kernel<<<gk, 128>>>(key,   WKw, WKb, (float*)pk, KDIM, 1);
    dim3 gv(LSEQ * BATCH / 16, 4);
    proj_kernel<<<gv, 128>>>(value, WVw, WVb, (float*)pv, DDIM, 0);
    dim3 gf(LSEQ / QT, BATCH);
    flash_kernel<<<gf, 256, smem>>>((const float*)pq, (const float*)pk,
                                    (const float*)pv, out);
}

// round 4
// speedup vs baseline: 2.7153x; 2.7153x over previous
#include <cuda_runtime.h>
#include <cuda_bf16.h>
#include <cstdint>
#include <math.h>

#define LSEQ 4096
#define BATCH 4
#define KD 128
#define DD 512

// ---------------- scratch (no allocation allowed) ----------------
__device__ __nv_bfloat16 g_qh[BATCH * LSEQ * KD];
__device__ __nv_bfloat16 g_ql[BATCH * LSEQ * KD];
__device__ __nv_bfloat16 g_kh[BATCH * LSEQ * KD];
__device__ __nv_bfloat16 g_kl[BATCH * LSEQ * KD];
__device__ __nv_bfloat16 g_vh[(size_t)BATCH * DD * LSEQ];   // [b][d][l]
__device__ __nv_bfloat16 g_vl[(size_t)BATCH * DD * LSEQ];

// ---------------- helpers ----------------
__device__ __forceinline__ uint32_t smem_u32(const void* p) {
    uint32_t a;
    asm("{ .reg .u64 t; cvta.to.shared.u64 t, %1; cvt.u32.u64 %0, t; }" : "=r"(a) : "l"(p));
    return a;
}

#define LDSM4(r, addr) \
    asm volatile("ldmatrix.sync.aligned.m8n8.x4.shared.b16 {%0,%1,%2,%3}, [%4];" \
        : "=r"((r)[0]), "=r"((r)[1]), "=r"((r)[2]), "=r"((r)[3]) : "r"(addr))

#define MMA(d, a, b0, b1) \
    asm volatile("mma.sync.aligned.m16n8k16.row.col.f32.bf16.bf16.f32 " \
        "{%0,%1,%2,%3}, {%4,%5,%6,%7}, {%8,%9}, {%0,%1,%2,%3};" \
        : "+f"((d)[0]), "+f"((d)[1]), "+f"((d)[2]), "+f"((d)[3]) \
        : "r"((a)[0]), "r"((a)[1]), "r"((a)[2]), "r"((a)[3]), "r"(b0), "r"(b1))

#define CP16(dst, src) \
    asm volatile("cp.async.cg.shared.global [%0], [%1], 16;" :: "r"(dst), "l"(src))
#define CP_COMMIT() asm volatile("cp.async.commit_group;" ::: "memory")
#define CP_WAIT1()  asm volatile("cp.async.wait_group 1;" ::: "memory")
#define CP_WAIT0()  asm volatile("cp.async.wait_group 0;" ::: "memory")

__device__ __forceinline__ unsigned short bf16bits(float x) {
    __nv_bfloat16 h = __float2bfloat16(x);
    return *reinterpret_cast<unsigned short*>(&h);
}
__device__ __forceinline__ float bf16val(unsigned short u) {
    __nv_bfloat16 h;
    *reinterpret_cast<unsigned short*>(&h) = u;
    return __bfloat162float(h);
}

// ---------------------------------------------------------------------------
// Projection Q/K: GEMM + bias + L2norm -> split bf16 hi/lo, [b][l][128]
// ---------------------------------------------------------------------------
__global__ __launch_bounds__(128) void proj_qk_kernel(
    const float* __restrict__ X, const float* __restrict__ W,
    const float* __restrict__ bias,
    __nv_bfloat16* __restrict__ outh, __nv_bfloat16* __restrict__ outl)
{
    __shared__ float xs[16][32];
    __shared__ float ws[128][36];
    __shared__ float outs[16][128];

    const int tid = threadIdx.x;
    const int m0 = blockIdx.x * 16;

    float acc[16];
#pragma unroll
    for (int r = 0; r < 16; r++) acc[r] = 0.f;

    for (int ck = 0; ck < 16; ck++) {
        __syncthreads();
        { int row = tid >> 3, c4 = tid & 7;
          *(float4*)&xs[row][c4 * 4] =
              *(const float4*)(X + (size_t)(m0 + row) * 512 + ck * 32 + c4 * 4); }
#pragma unroll
        for (int i = 0; i < 8; i++) {
            int f = tid + 128 * i, row = f >> 3, c4 = f & 7;
            *(float4*)&ws[row][c4 * 4] =
                *(const float4*)(W + (size_t)row * 512 + ck * 32 + c4 * 4);
        }
        __syncthreads();
#pragma unroll
        for (int d4 = 0; d4 < 8; d4++) {
            float4 w4 = *(float4*)&ws[tid][d4 * 4];
#pragma unroll
            for (int r = 0; r < 16; r++) {
                float4 x4 = *(float4*)&xs[r][d4 * 4];
                acc[r] += x4.x * w4.x + x4.y * w4.y + x4.z * w4.z + x4.w * w4.w;
            }
        }
    }

    float bv = bias[tid];
#pragma unroll
    for (int r = 0; r < 16; r++) outs[r][tid] = acc[r] + bv;
    __syncthreads();

    int w = tid >> 5, lane = tid & 31;
#pragma unroll
    for (int r = 0; r < 4; r++) {
        int rowi = w * 4 + r;
        float4 v = *(float4*)&outs[rowi][lane * 4];
        float ss = v.x * v.x + v.y * v.y + v.z * v.z + v.w * v.w;
#pragma unroll
        for (int o = 16; o >= 1; o >>= 1)
            ss += __shfl_xor_sync(0xffffffffu, ss, o);
        float sc = 1.f / fmaxf(sqrtf(ss), 1e-12f);
        int m = m0 + rowi, li = m >> 2, bi = m & 3;
        float f0 = v.x * sc, f1 = v.y * sc, f2 = v.z * sc, f3 = v.w * sc;
        unsigned short h0 = bf16bits(f0), h1 = bf16bits(f1),
                       h2 = bf16bits(f2), h3 = bf16bits(f3);
        unsigned short l0 = bf16bits(f0 - bf16val(h0)), l1 = bf16bits(f1 - bf16val(h1)),
                       l2 = bf16bits(f2 - bf16val(h2)), l3 = bf16bits(f3 - bf16val(h3));
        size_t idx = ((size_t)bi * LSEQ + li) * KD + lane * 4;
        uint2 H = make_uint2((uint32_t)h0 | ((uint32_t)h1 << 16),
                             (uint32_t)h2 | ((uint32_t)h3 << 16));
        uint2 L = make_uint2((uint32_t)l0 | ((uint32_t)l1 << 16),
                             (uint32_t)l2 | ((uint32_t)l3 << 16));
        *(uint2*)&outh[idx] = H;
        *(uint2*)&outl[idx] = L;
    }
}

// ---------------------------------------------------------------------------
// Projection V: GEMM + bias -> split bf16 hi/lo TRANSPOSED [b][d][l]
// ---------------------------------------------------------------------------
__global__ __launch_bounds__(128) void proj_v_kernel(
    const float* __restrict__ X, const float* __restrict__ W,
    const float* __restrict__ bias,
    __nv_bfloat16* __restrict__ outh, __nv_bfloat16* __restrict__ outl)
{
    __shared__ float xs[16][32];
    __shared__ float ws[128][36];
    __shared__ float outs[16][128];

    const int tid = threadIdx.x;
    const int m0 = blockIdx.x * 16;
    const int n0 = blockIdx.y * 128;

    float acc[16];
#pragma unroll
    for (int r = 0; r < 16; r++) acc[r] = 0.f;

    for (int ck = 0; ck < 16; ck++) {
        __syncthreads();
        { int row = tid >> 3, c4 = tid & 7;
          *(float4*)&xs[row][c4 * 4] =
              *(const float4*)(X + (size_t)(m0 + row) * 512 + ck * 32 + c4 * 4); }
#pragma unroll
        for (int i = 0; i < 8; i++) {
            int f = tid + 128 * i, row = f >> 3, c4 = f & 7;
            *(float4*)&ws[row][c4 * 4] =
                *(const float4*)(W + (size_t)(n0 + row) * 512 + ck * 32 + c4 * 4);
        }
        __syncthreads();
#pragma unroll
        for (int d4 = 0; d4 < 8; d4++) {
            float4 w4 = *(float4*)&ws[tid][d4 * 4];
#pragma unroll
            for (int r = 0; r < 16; r++) {
                float4 x4 = *(float4*)&xs[r][d4 * 4];
                acc[r] += x4.x * w4.x + x4.y * w4.y + x4.z * w4.z + x4.w * w4.w;
            }
        }
    }

    float bv = bias[n0 + tid];
#pragma unroll
    for (int r = 0; r < 16; r++) outs[r][tid] = acc[r] + bv;
    __syncthreads();

    int li0 = m0 >> 2;
#pragma unroll
    for (int bb = 0; bb < 4; bb++) {
        float f0 = outs[0 + bb][tid], f1 = outs[4 + bb][tid],
              f2 = outs[8 + bb][tid], f3 = outs[12 + bb][tid];
        unsigned short h0 = bf16bits(f0), h1 = bf16bits(f1),
                       h2 = bf16bits(f2), h3 = bf16bits(f3);
        unsigned short l0 = bf16bits(f0 - bf16val(h0)), l1 = bf16bits(f1 - bf16val(h1)),
                       l2 = bf16bits(f2 - bf16val(h2)), l3 = bf16bits(f3 - bf16val(h3));
        size_t idx = ((size_t)bb * DD + n0 + tid) * LSEQ + li0;
        uint2 H = make_uint2((uint32_t)h0 | ((uint32_t)h1 << 16),
                             (uint32_t)h2 | ((uint32_t)h3 << 16));
        uint2 L = make_uint2((uint32_t)l0 | ((uint32_t)l1 << 16),
                             (uint32_t)l2 | ((uint32_t)l3 << 16));
        *(uint2*)&outh[idx] = H;
        *(uint2*)&outl[idx] = L;
    }
}

// ---------------------------------------------------------------------------
// Flash attention on mma.sync (HMMA), split-bf16, fixed exp shift.
// Grid (32 qtiles of 128 rows, 4 batch, 2 d-halves of 256). 256 threads.
// Warp w owns q rows [q0 + 16w, +16). S-tile = 64 keys, two 32-col halves.
// SMEM: double-buffered K hi/lo [64][128] (272B rows) + V^T hi/lo [256][64]
// (144B rows). ldmatrix strides mod 128 = 16 -> conflict-free.
// ---------------------------------------------------------------------------
#define K_ROWB 272
#define K_HL   17408        // 64*272
#define K_STG  34816        // hi+lo per stage
#define V_ROWB 144
#define V_HL   36864        // 256*144
#define V_STG  73728
#define SM_K   0
#define SM_V   69632        // 2*K_STG
#define SM_TOT 217088       // SM_V + 2*V_STG

__global__ __launch_bounds__(256, 1) void flash_mma_kernel(float* __restrict__ out)
{
    extern __shared__ char smem[];
    const uint32_t sb = smem_u32(smem);
    const int tid = threadIdx.x;
    const int lane = tid & 31;
    const int w = tid >> 5;
    const int q0 = blockIdx.x * 128;
    const int b = blockIdx.y;
    const int dh = blockIdx.z;

    // ldmatrix lane pattern: lanes 0-7 rows 0-7 col+0; 8-15 rows 8-15 col+0;
    // 16-23 rows 0-7 col+8; 24-31 rows 8-15 col+8.
    const int rowpat = ((lane >> 3) & 1) * 8 + (lane & 7);
    const int colpat = (lane >> 4) * 8;

    // ---- stage Q through K-stage0 buffer, build persistent A fragments ----
    uint32_t qa_h[8][4], qa_l[8][4];
#pragma unroll 1
    for (int pass = 0; pass < 2; pass++) {
        __syncthreads();
        for (int idx = tid; idx < 1024; idx += 256) {
            int r = idx >> 4, ch = idx & 15;
            size_t g = ((size_t)b * LSEQ + q0 + pass * 64 + r) * KD + ch * 8;
            *(uint4*)(smem + SM_K + r * K_ROWB + ch * 16) = *(const uint4*)(g_qh + g);
            *(uint4*)(smem + SM_K + K_HL + r * K_ROWB + ch * 16) = *(const uint4*)(g_ql + g);
        }
        __syncthreads();
        if ((w >> 2) == pass) {
            uint32_t base = sb + SM_K + (uint32_t)(((w & 3) * 16 + rowpat) * K_ROWB + colpat * 2);
#pragma unroll
            for (int kt = 0; kt < 8; kt++) {
                LDSM4(qa_h[kt], base + kt * 32);
                LDSM4(qa_l[kt], base + K_HL + kt * 32);
            }
        }
    }
    __syncthreads();

    float O[32][4];
#pragma unroll
    for (int i = 0; i < 32; i++)
#pragma unroll
        for (int j = 0; j < 4; j++) O[i][j] = 0.f;
    float lsum0 = 0.f, lsum1 = 0.f;

    auto load_tile = [&](int st, int stg) {
        size_t kbase = ((size_t)b * LSEQ + st * 64) * KD;
        uint32_t kd = sb + SM_K + stg * K_STG;
#pragma unroll
        for (int i = 0; i < 4; i++) {
            int idx = tid + i * 256;
            int r = idx >> 4, ch = idx & 15;
            uint32_t d = kd + r * K_ROWB + ch * 16;
            const __nv_bfloat16* s = g_kh + kbase + (size_t)r * KD + ch * 8;
            CP16(d, s);
            CP16(d + K_HL, g_kl + kbase + (size_t)r * KD + ch * 8);
        }
        size_t vbase = ((size_t)b * DD + dh * 256) * LSEQ + st * 64;
        uint32_t vd = sb + SM_V + stg * V_STG;
#pragma unroll
        for (int i = 0; i < 8; i++) {
            int idx = tid + i * 256;
            int r = idx >> 3, ch = idx & 7;
            uint32_t d = vd + r * V_ROWB + ch * 16;
            CP16(d, g_vh + vbase + (size_t)r * LSEQ + ch * 8);
            CP16(d + V_HL, g_vl + vbase + (size_t)r * LSEQ + ch * 8);
        }
    };

    load_tile(0, 0);
    CP_COMMIT();

#pragma unroll 1
    for (int st = 0; st < 64; st++) {
        const int stg = st & 1;
        if (st + 1 < 64) { load_tile(st + 1, stg ^ 1); CP_COMMIT(); CP_WAIT1(); }
        else             { CP_WAIT0(); }
        __syncthreads();

        const uint32_t kb = sb + SM_K + stg * K_STG + (uint32_t)(rowpat * K_ROWB + colpat * 2);
        const uint32_t vb = sb + SM_V + stg * V_STG + (uint32_t)(rowpat * V_ROWB + colpat * 2);

#pragma unroll
        for (int h = 0; h < 2; h++) {
            // ---- QK: S[16 rows][32 cols] ----
            float s[4][4];
#pragma unroll
            for (int nt = 0; nt < 4; nt++)
#pragma unroll
                for (int j = 0; j < 4; j++) s[nt][j] = 0.f;

#pragma unroll
            for (int kt = 0; kt < 8; kt++) {
#pragma unroll
                for (int c = 0; c < 2; c++) {
                    uint32_t a = kb + (uint32_t)((h * 32 + c * 16) * K_ROWB + kt * 32);
                    uint32_t kh4[4], kl4[4];
                    LDSM4(kh4, a);
                    LDSM4(kl4, a + K_HL);
                    MMA(s[2 * c],     qa_h[kt], kh4[0], kh4[2]);
                    MMA(s[2 * c],     qa_h[kt], kl4[0], kl4[2]);
                    MMA(s[2 * c],     qa_l[kt], kh4[0], kh4[2]);
                    MMA(s[2 * c + 1], qa_h[kt], kh4[1], kh4[3]);
                    MMA(s[2 * c + 1], qa_h[kt], kl4[1], kl4[3]);
                    MMA(s[2 * c + 1], qa_l[kt], kh4[1], kh4[3]);
                }
            }

            // ---- p = exp(30 s - 30); pack A fragments hi/lo ----
            uint32_t pah[2][4], pal[2][4];
#pragma unroll
            for (int nt = 0; nt < 4; nt++) {
                float p0 = __expf(fmaf(30.f, s[nt][0], -30.f));
                float p1 = __expf(fmaf(30.f, s[nt][1], -30.f));
                float p2 = __expf(fmaf(30.f, s[nt][2], -30.f));
                float p3 = __expf(fmaf(30.f, s[nt][3], -30.f));
                lsum0 += p0 + p1;
                lsum1 += p2 + p3;
                __nv_bfloat162 h01 = __floats2bfloat162_rn(p0, p1);
                __nv_bfloat162 h23 = __floats2bfloat162_rn(p2, p3);
                float r0 = p0 - __bfloat162float(h01.x);
                float r1 = p1 - __bfloat162float(h01.y);
                float r2 = p2 - __bfloat162float(h23.x);
                float r3 = p3 - __bfloat162float(h23.y);
                __nv_bfloat162 l01 = __floats2bfloat162_rn(r0, r1);
                __nv_bfloat162 l23 = __floats2bfloat162_rn(r2, r3);
                int t = nt >> 1, e = (nt & 1) * 2;
                pah[t][e + 0] = *reinterpret_cast<uint32_t*>(&h01);
                pah[t][e + 1] = *reinterpret_cast<uint32_t*>(&h23);
                pal[t][e + 0] = *reinterpret_cast<uint32_t*>(&l01);
                pal[t][e + 1] = *reinterpret_cast<uint32_t*>(&l23);
            }

            // ---- PV: O += P . V ----
#pragma unroll
            for (int t = 0; t < 2; t++) {
                uint32_t kofs = (uint32_t)((h * 2 + t) * 32);
#pragma unroll
                for (int nc = 0; nc < 16; nc++) {
                    uint32_t a = vb + (uint32_t)(nc * 16 * V_ROWB) + kofs;
                    uint32_t vh4[4], vl4[4];
                    LDSM4(vh4, a);
                    LDSM4(vl4, a + V_HL);
                    MMA(O[2 * nc],     pah[t], vh4[0], vh4[2]);
                    MMA(O[2 * nc],     pah[t], vl4[0], vl4[2]);
                    MMA(O[2 * nc],     pal[t], vh4[0], vh4[2]);
                    MMA(O[2 * nc + 1], pah[t], vh4[1], vh4[3]);
                    MMA(O[2 * nc + 1], pah[t], vl4[1], vl4[3]);
                    MMA(O[2 * nc + 1], pal[t], vh4[1], vh4[3]);
                }
            }
        }
        __syncthreads();
    }

    // ---- epilogue ----
    lsum0 += __shfl_xor_sync(0xffffffffu, lsum0, 1);
    lsum0 += __shfl_xor_sync(0xffffffffu, lsum0, 2);
    lsum1 += __shfl_xor_sync(0xffffffffu, lsum1, 1);
    lsum1 += __shfl_xor_sync(0xffffffffu, lsum1, 2);
    float inv0 = 1.f / lsum0, inv1 = 1.f / lsum1;

    int r0 = q0 + w * 16 + (lane >> 2);
    int cb = dh * 256 + (lane & 3) * 2;
#pragma unroll
    for (int nt = 0; nt < 32; nt++) {
        int col = cb + nt * 8;
        float2 o0 = make_float2(O[nt][0] * inv0, O[nt][1] * inv0);
        float2 o1 = make_float2(O[nt][2] * inv1, O[nt][3] * inv1);
        *(float2*)(out + ((size_t)r0 * BATCH + b) * DD + col) = o0;
        *(float2*)(out + ((size_t)(r0 + 8) * BATCH + b) * DD + col) = o1;
    }
}

// ---------------------------------------------------------------------------
extern "C" void kernel_launch(void* const* d_in, const int* in_sizes, int n_in,
                              void* d_out, int out_size)
{
    const float* query = (const float*)d_in[0];
    const float* key   = (const float*)d_in[1];
    const float* value = (const float*)d_in[2];
    const float* WKw   = (const float*)d_in[3];
    const float* WKb   = (const float*)d_in[4];
    const float* WVw   = (const float*)d_in[5];
    const float* WVb   = (const float*)d_in[6];
    float* out = (float*)d_out;
    (void)in_sizes; (void)n_in; (void)out_size;

    void *qh, *ql, *kh, *kl, *vh, *vl;
    cudaGetSymbolAddress(&qh, g_qh); cudaGetSymbolAddress(&ql, g_ql);
    cudaGetSymbolAddress(&kh, g_kh); cudaGetSymbolAddress(&kl, g_kl);
    cudaGetSymbolAddress(&vh, g_vh); cudaGetSymbolAddress(&vl, g_vl);

    cudaFuncSetAttribute(flash_mma_kernel,
                         cudaFuncAttributeMaxDynamicSharedMemorySize, SM_TOT);

    dim3 gqk(LSEQ * BATCH / 16);
    proj_qk_kernel<<<gqk, 128>>>(query, WKw, WKb,
                                 (__nv_bfloat16*)qh, (__nv_bfloat16*)ql);
    proj_qk_kernel<<<gqk, 128>>>(key, WKw, WKb,
                                 (__nv_bfloat16*)kh, (__nv_bfloat16*)kl);
    dim3 gv(LSEQ * BATCH / 16, 4);
    proj_v_kernel<<<gv, 128>>>(value, WVw, WVb,
                               (__nv_bfloat16*)vh, (__nv_bfloat16*)vl);
    dim3 gf(LSEQ / 128, BATCH, 2);
    flash_mma_kernel<<<gf, 256, SM_TOT>>>(out);
}

// round 5
// speedup vs baseline: 2.9151x; 1.0736x over previous
#include <cuda_runtime.h>
#include <cuda_bf16.h>
#include <cstdint>
#include <math.h>

#define LSEQ 4096
#define BATCH 4
#define KD 128
#define DD 512

// ---------------- scratch (no allocation allowed) ----------------
__device__ __nv_bfloat16 g_qh[BATCH * LSEQ * KD];
__device__ __nv_bfloat16 g_ql[BATCH * LSEQ * KD];
__device__ __nv_bfloat16 g_kh[BATCH * LSEQ * KD];
__device__ __nv_bfloat16 g_kl[BATCH * LSEQ * KD];
__device__ __nv_bfloat16 g_vh[(size_t)BATCH * DD * LSEQ];   // [b][d][l]
__device__ __nv_bfloat16 g_vl[(size_t)BATCH * DD * LSEQ];
// P blocked: [b][qt(64)][st(64)][64 rows][64 cols]
__device__ __nv_bfloat16 g_ph[(size_t)BATCH * LSEQ * LSEQ];
__device__ __nv_bfloat16 g_pl[(size_t)BATCH * LSEQ * LSEQ];
__device__ float g_lsum[BATCH * LSEQ];

// ---------------- helpers ----------------
__device__ __forceinline__ uint32_t smem_u32(const void* p) {
    uint32_t a;
    asm("{ .reg .u64 t; cvta.to.shared.u64 t, %1; cvt.u32.u64 %0, t; }" : "=r"(a) : "l"(p));
    return a;
}

#define LDSM4(r, addr) \
    asm volatile("ldmatrix.sync.aligned.m8n8.x4.shared.b16 {%0,%1,%2,%3}, [%4];" \
        : "=r"((r)[0]), "=r"((r)[1]), "=r"((r)[2]), "=r"((r)[3]) : "r"(addr))

#define MMA(d, a, b0, b1) \
    asm volatile("mma.sync.aligned.m16n8k16.row.col.f32.bf16.bf16.f32 " \
        "{%0,%1,%2,%3}, {%4,%5,%6,%7}, {%8,%9}, {%0,%1,%2,%3};" \
        : "+f"((d)[0]), "+f"((d)[1]), "+f"((d)[2]), "+f"((d)[3]) \
        : "r"((a)[0]), "r"((a)[1]), "r"((a)[2]), "r"((a)[3]), "r"(b0), "r"(b1))

#define CP16(dst, src) \
    asm volatile("cp.async.cg.shared.global [%0], [%1], 16;" :: "r"(dst), "l"(src))
#define CP_COMMIT() asm volatile("cp.async.commit_group;" ::: "memory")
#define CP_WAIT1()  asm volatile("cp.async.wait_group 1;" ::: "memory")
#define CP_WAIT0()  asm volatile("cp.async.wait_group 0;" ::: "memory")

__device__ __forceinline__ unsigned short bf16bits(float x) {
    __nv_bfloat16 h = __float2bfloat16(x);
    return *reinterpret_cast<unsigned short*>(&h);
}
__device__ __forceinline__ float bf16val(unsigned short u) {
    __nv_bfloat16 h;
    *reinterpret_cast<unsigned short*>(&h) = u;
    return __bfloat162float(h);
}

// ---------------------------------------------------------------------------
// Projection Q/K: GEMM + bias + L2norm -> split bf16 hi/lo, [b][l][128]
// ---------------------------------------------------------------------------
__global__ __launch_bounds__(128) void proj_qk_kernel(
    const float* __restrict__ X, const float* __restrict__ W,
    const float* __restrict__ bias,
    __nv_bfloat16* __restrict__ outh, __nv_bfloat16* __restrict__ outl)
{
    __shared__ float xs[16][32];
    __shared__ float ws[128][36];
    __shared__ float outs[16][128];

    const int tid = threadIdx.x;
    const int m0 = blockIdx.x * 16;

    float acc[16];
#pragma unroll
    for (int r = 0; r < 16; r++) acc[r] = 0.f;

    for (int ck = 0; ck < 16; ck++) {
        __syncthreads();
        { int row = tid >> 3, c4 = tid & 7;
          *(float4*)&xs[row][c4 * 4] =
              *(const float4*)(X + (size_t)(m0 + row) * 512 + ck * 32 + c4 * 4); }
#pragma unroll
        for (int i = 0; i < 8; i++) {
            int f = tid + 128 * i, row = f >> 3, c4 = f & 7;
            *(float4*)&ws[row][c4 * 4] =
                *(const float4*)(W + (size_t)row * 512 + ck * 32 + c4 * 4);
        }
        __syncthreads();
#pragma unroll
        for (int d4 = 0; d4 < 8; d4++) {
            float4 w4 = *(float4*)&ws[tid][d4 * 4];
#pragma unroll
            for (int r = 0; r < 16; r++) {
                float4 x4 = *(float4*)&xs[r][d4 * 4];
                acc[r] += x4.x * w4.x + x4.y * w4.y + x4.z * w4.z + x4.w * w4.w;
            }
        }
    }

    float bv = bias[tid];
#pragma unroll
    for (int r = 0; r < 16; r++) outs[r][tid] = acc[r] + bv;
    __syncthreads();

    int w = tid >> 5, lane = tid & 31;
#pragma unroll
    for (int r = 0; r < 4; r++) {
        int rowi = w * 4 + r;
        float4 v = *(float4*)&outs[rowi][lane * 4];
        float ss = v.x * v.x + v.y * v.y + v.z * v.z + v.w * v.w;
#pragma unroll
        for (int o = 16; o >= 1; o >>= 1)
            ss += __shfl_xor_sync(0xffffffffu, ss, o);
        float sc = 1.f / fmaxf(sqrtf(ss), 1e-12f);
        int m = m0 + rowi, li = m >> 2, bi = m & 3;
        float f0 = v.x * sc, f1 = v.y * sc, f2 = v.z * sc, f3 = v.w * sc;
        unsigned short h0 = bf16bits(f0), h1 = bf16bits(f1),
                       h2 = bf16bits(f2), h3 = bf16bits(f3);
        unsigned short l0 = bf16bits(f0 - bf16val(h0)), l1 = bf16bits(f1 - bf16val(h1)),
                       l2 = bf16bits(f2 - bf16val(h2)), l3 = bf16bits(f3 - bf16val(h3));
        size_t idx = ((size_t)bi * LSEQ + li) * KD + lane * 4;
        uint2 H = make_uint2((uint32_t)h0 | ((uint32_t)h1 << 16),
                             (uint32_t)h2 | ((uint32_t)h3 << 16));
        uint2 L = make_uint2((uint32_t)l0 | ((uint32_t)l1 << 16),
                             (uint32_t)l2 | ((uint32_t)l3 << 16));
        *(uint2*)&outh[idx] = H;
        *(uint2*)&outl[idx] = L;
    }
}

// ---------------------------------------------------------------------------
// Projection V: GEMM + bias -> split bf16 hi/lo TRANSPOSED [b][d][l]
// ---------------------------------------------------------------------------
__global__ __launch_bounds__(128) void proj_v_kernel(
    const float* __restrict__ X, const float* __restrict__ W,
    const float* __restrict__ bias,
    __nv_bfloat16* __restrict__ outh, __nv_bfloat16* __restrict__ outl)
{
    __shared__ float xs[16][32];
    __shared__ float ws[128][36];
    __shared__ float outs[16][128];

    const int tid = threadIdx.x;
    const int m0 = blockIdx.x * 16;
    const int n0 = blockIdx.y * 128;

    float acc[16];
#pragma unroll
    for (int r = 0; r < 16; r++) acc[r] = 0.f;

    for (int ck = 0; ck < 16; ck++) {
        __syncthreads();
        { int row = tid >> 3, c4 = tid & 7;
          *(float4*)&xs[row][c4 * 4] =
              *(const float4*)(X + (size_t)(m0 + row) * 512 + ck * 32 + c4 * 4); }
#pragma unroll
        for (int i = 0; i < 8; i++) {
            int f = tid + 128 * i, row = f >> 3, c4 = f & 7;
            *(float4*)&ws[row][c4 * 4] =
                *(const float4*)(W + (size_t)(n0 + row) * 512 + ck * 32 + c4 * 4);
        }
        __syncthreads();
#pragma unroll
        for (int d4 = 0; d4 < 8; d4++) {
            float4 w4 = *(float4*)&ws[tid][d4 * 4];
#pragma unroll
            for (int r = 0; r < 16; r++) {
                float4 x4 = *(float4*)&xs[r][d4 * 4];
                acc[r] += x4.x * w4.x + x4.y * w4.y + x4.z * w4.z + x4.w * w4.w;
            }
        }
    }

    float bv = bias[n0 + tid];
#pragma unroll
    for (int r = 0; r < 16; r++) outs[r][tid] = acc[r] + bv;
    __syncthreads();

    int li0 = m0 >> 2;
#pragma unroll
    for (int bb = 0; bb < 4; bb++) {
        float f0 = outs[0 + bb][tid], f1 = outs[4 + bb][tid],
              f2 = outs[8 + bb][tid], f3 = outs[12 + bb][tid];
        unsigned short h0 = bf16bits(f0), h1 = bf16bits(f1),
                       h2 = bf16bits(f2), h3 = bf16bits(f3);
        unsigned short l0 = bf16bits(f0 - bf16val(h0)), l1 = bf16bits(f1 - bf16val(h1)),
                       l2 = bf16bits(f2 - bf16val(h2)), l3 = bf16bits(f3 - bf16val(h3));
        size_t idx = ((size_t)bb * DD + n0 + tid) * LSEQ + li0;
        uint2 H = make_uint2((uint32_t)h0 | ((uint32_t)h1 << 16),
                             (uint32_t)h2 | ((uint32_t)h3 << 16));
        uint2 L = make_uint2((uint32_t)l0 | ((uint32_t)l1 << 16),
                             (uint32_t)l2 | ((uint32_t)l3 << 16));
        *(uint2*)&outh[idx] = H;
        *(uint2*)&outl[idx] = L;
    }
}

// ---------------------------------------------------------------------------
// Phase A: QK + softmax, P materialized. Grid (64 qt, 4 b), 256 thr, 2 CTA/SM.
// Warp: rows 16g..16g+15 (g=w&3), keys 32h..32h+31 (h=w>>2) of the 64-key tile.
// ---------------------------------------------------------------------------
#define A_KRB 272
#define A_KHL 17408          // 64*272
#define A_KSTG 34816
#define A_SMK 0              // 2 stages = 69632
#define A_SMP 69632          // P double buffer: 2 x (hi 8192 + lo 8192)
#define A_PBUF 16384
#define A_TOT 102400

__global__ __launch_bounds__(256, 2) void qk_kernel()
{
    extern __shared__ char smem[];
    const uint32_t sb = smem_u32(smem);
    const int tid = threadIdx.x;
    const int lane = tid & 31;
    const int w = tid >> 5;
    const int qt = blockIdx.x;
    const int b = blockIdx.y;
    const int g = w & 3, h = w >> 2;

    const int rowpat = ((lane >> 3) & 1) * 8 + (lane & 7);
    const int colpat = (lane >> 4) * 8;

    // stage Q (64 rows x 128 k, hi/lo) into K stage 0, build persistent A frags
    for (int idx = tid; idx < 1024; idx += 256) {
        int r = idx >> 4, ch = idx & 15;
        size_t gofs = ((size_t)b * LSEQ + qt * 64 + r) * KD + ch * 8;
        *(uint4*)(smem + A_SMK + r * A_KRB + ch * 16) = *(const uint4*)(g_qh + gofs);
        *(uint4*)(smem + A_SMK + A_KHL + r * A_KRB + ch * 16) = *(const uint4*)(g_ql + gofs);
    }
    __syncthreads();
    uint32_t qa_h[8][4], qa_l[8][4];
    {
        uint32_t base = sb + A_SMK + (uint32_t)((g * 16 + rowpat) * A_KRB + colpat * 2);
#pragma unroll
        for (int kt = 0; kt < 8; kt++) {
            LDSM4(qa_h[kt], base + kt * 32);
            LDSM4(qa_l[kt], base + A_KHL + kt * 32);
        }
    }
    __syncthreads();

    auto load_k = [&](int st, int stg) {
        size_t kb = ((size_t)b * LSEQ + st * 64) * KD;
        uint32_t kd = sb + A_SMK + stg * A_KSTG;
#pragma unroll
        for (int i = 0; i < 4; i++) {
            int idx = tid + i * 256;
            int r = idx >> 4, ch = idx & 15;
            uint32_t d = kd + r * A_KRB + ch * 16;
            CP16(d, g_kh + kb + (size_t)r * KD + ch * 8);
            CP16(d + A_KHL, g_kl + kb + (size_t)r * KD + ch * 8);
        }
    };

    load_k(0, 0);
    CP_COMMIT();

    float la = 0.f, lb = 0.f;
    const int lr = lane >> 2;

#pragma unroll 1
    for (int st = 0; st < 64; st++) {
        const int stg = st & 1;
        if (st + 1 < 64) { load_k(st + 1, stg ^ 1); CP_COMMIT(); CP_WAIT1(); }
        else             { CP_WAIT0(); }
        __syncthreads();

        const uint32_t kb = sb + A_SMK + stg * A_KSTG
                          + (uint32_t)((h * 32 + rowpat) * A_KRB + colpat * 2);
        float s[4][4];
#pragma unroll
        for (int nt = 0; nt < 4; nt++)
#pragma unroll
            for (int j = 0; j < 4; j++) s[nt][j] = 0.f;

#pragma unroll
        for (int kt = 0; kt < 8; kt++) {
#pragma unroll
            for (int c = 0; c < 2; c++) {
                uint32_t a = kb + (uint32_t)(c * 16 * A_KRB + kt * 32);
                uint32_t kh4[4], kl4[4];
                LDSM4(kh4, a);
                LDSM4(kl4, a + A_KHL);
                MMA(s[2 * c],     qa_h[kt], kh4[0], kh4[2]);
                MMA(s[2 * c + 1], qa_h[kt], kh4[1], kh4[3]);
                MMA(s[2 * c],     qa_h[kt], kl4[0], kl4[2]);
                MMA(s[2 * c + 1], qa_h[kt], kl4[1], kl4[3]);
                MMA(s[2 * c],     qa_l[kt], kh4[0], kh4[2]);
                MMA(s[2 * c + 1], qa_l[kt], kh4[1], kh4[3]);
            }
        }

        // softmax + pack into P smem buffer (parity stg)
        const uint32_t pbase = sb + A_SMP + stg * A_PBUF;
#pragma unroll
        for (int nt = 0; nt < 4; nt++) {
            float p0 = __expf(fmaf(30.f, s[nt][0], -30.f));
            float p1 = __expf(fmaf(30.f, s[nt][1], -30.f));
            float p2 = __expf(fmaf(30.f, s[nt][2], -30.f));
            float p3 = __expf(fmaf(30.f, s[nt][3], -30.f));
            la += p0 + p1;
            lb += p2 + p3;
            __nv_bfloat162 h01 = __floats2bfloat162_rn(p0, p1);
            __nv_bfloat162 h23 = __floats2bfloat162_rn(p2, p3);
            float r0 = p0 - __bfloat162float(h01.x);
            float r1 = p1 - __bfloat162float(h01.y);
            float r2 = p2 - __bfloat162float(h23.x);
            float r3 = p3 - __bfloat162float(h23.y);
            __nv_bfloat162 l01 = __floats2bfloat162_rn(r0, r1);
            __nv_bfloat162 l23 = __floats2bfloat162_rn(r2, r3);
            uint32_t col2 = (uint32_t)((h * 32 + nt * 8 + (lane & 3) * 2) * 2);
            uint32_t a0 = pbase + (uint32_t)((g * 16 + lr) * 128) + col2;
            uint32_t a1 = pbase + (uint32_t)((g * 16 + lr + 8) * 128) + col2;
            asm volatile("st.shared.b32 [%0], %1;" :: "r"(a0), "r"(*(uint32_t*)&h01));
            asm volatile("st.shared.b32 [%0], %1;" :: "r"(a1), "r"(*(uint32_t*)&h23));
            asm volatile("st.shared.b32 [%0], %1;" :: "r"(a0 + 8192), "r"(*(uint32_t*)&l01));
            asm volatile("st.shared.b32 [%0], %1;" :: "r"(a1 + 8192), "r"(*(uint32_t*)&l23));
        }
        __syncthreads();

        // coalesced P store: block (b, qt, st): 64x64 hi + lo
        size_t blk = (((size_t)b * 64 + qt) * 64 + st) * 4096;
#pragma unroll
        for (int j = 0; j < 2; j++) {
            int flat = tid + j * 256;
            int r = flat >> 3, c16 = flat & 7;
            uint4 vH = *(uint4*)(smem + (pbase - sb) + r * 128 + c16 * 16);
            uint4 vL = *(uint4*)(smem + (pbase - sb) + 8192 + r * 128 + c16 * 16);
            *(uint4*)(g_ph + blk + r * 64 + c16 * 8) = vH;
            *(uint4*)(g_pl + blk + r * 64 + c16 * 8) = vL;
        }
    }

    // row sums: reduce over lane&3, combine warp halves via SMEM
    la += __shfl_xor_sync(0xffffffffu, la, 1);
    la += __shfl_xor_sync(0xffffffffu, la, 2);
    lb += __shfl_xor_sync(0xffffffffu, lb, 1);
    lb += __shfl_xor_sync(0xffffffffu, lb, 2);
    __syncthreads();
    float* ls = (float*)(smem + A_SMP);
    if ((lane & 3) == 0) {
        ls[(g * 16 + lr) * 2 + h] = la;
        ls[(g * 16 + lr + 8) * 2 + h] = lb;
    }
    __syncthreads();
    if (tid < 64)
        g_lsum[b * LSEQ + qt * 64 + tid] = ls[tid * 2] + ls[tid * 2 + 1];
}

// ---------------------------------------------------------------------------
// Phase B: O = P.V (split bf16, 3 MMA), pure GEMM over k=4096.
// Grid (32 qtiles of 128, 4 b, 2 dh). 256 thr, warp = 16 rows x 256 d.
// ---------------------------------------------------------------------------
#define B_PRB 144
#define B_PHL 18432          // 128*144
#define B_PSTG 36864
#define B_SMP 0              // 2 stages = 73728
#define B_VRB 144
#define B_VHL 36864          // 256*144
#define B_VSTG 73728
#define B_SMV 73728          // 2 stages = 147456
#define B_TOT 221184

__global__ __launch_bounds__(256, 1) void pv_kernel(float* __restrict__ out)
{
    extern __shared__ char smem[];
    const uint32_t sb = smem_u32(smem);
    const int tid = threadIdx.x;
    const int lane = tid & 31;
    const int w = tid >> 5;
    const int qX = blockIdx.x;
    const int b = blockIdx.y;
    const int dh = blockIdx.z;

    const int rowpat = ((lane >> 3) & 1) * 8 + (lane & 7);
    const int colpat = (lane >> 4) * 8;

    float O[32][4];
#pragma unroll
    for (int i = 0; i < 32; i++)
#pragma unroll
        for (int j = 0; j < 4; j++) O[i][j] = 0.f;

    auto load_chunk = [&](int kc, int stg) {
        size_t blkA = (((size_t)b * 64 + qX * 2) * 64 + kc) * 4096;
        uint32_t pd = sb + B_SMP + stg * B_PSTG;
#pragma unroll
        for (int i = 0; i < 4; i++) {
            int idx = tid + i * 256;
            int r = idx >> 3, c16 = idx & 7;
            size_t src = blkA + ((r < 64) ? (size_t)(r * 64)
                                          : (size_t)(64 * 4096 + (r - 64) * 64)) + c16 * 8;
            uint32_t d = pd + r * B_PRB + c16 * 16;
            CP16(d, g_ph + src);
            CP16(d + B_PHL, g_pl + src);
        }
        size_t vb = ((size_t)b * DD + dh * 256) * LSEQ + kc * 64;
        uint32_t vd = sb + B_SMV + stg * B_VSTG;
#pragma unroll
        for (int i = 0; i < 8; i++) {
            int idx = tid + i * 256;
            int r = idx >> 3, c16 = idx & 7;
            uint32_t d = vd + r * B_VRB + c16 * 16;
            CP16(d, g_vh + vb + (size_t)r * LSEQ + c16 * 8);
            CP16(d + B_VHL, g_vl + vb + (size_t)r * LSEQ + c16 * 8);
        }
    };

    load_chunk(0, 0);
    CP_COMMIT();

#pragma unroll 1
    for (int kc = 0; kc < 64; kc++) {
        const int stg = kc & 1;
        if (kc + 1 < 64) { load_chunk(kc + 1, stg ^ 1); CP_COMMIT(); CP_WAIT1(); }
        else             { CP_WAIT0(); }
        __syncthreads();

        const uint32_t pb = sb + B_SMP + stg * B_PSTG
                          + (uint32_t)((w * 16 + rowpat) * B_PRB + colpat * 2);
        const uint32_t vbs = sb + B_SMV + stg * B_VSTG
                           + (uint32_t)(rowpat * B_VRB + colpat * 2);

#pragma unroll
        for (int kt = 0; kt < 4; kt++) {
            uint32_t pah[4], pal[4];
            LDSM4(pah, pb + kt * 32);
            LDSM4(pal, pb + B_PHL + kt * 32);
#pragma unroll
            for (int nc = 0; nc < 16; nc++) {
                uint32_t a = vbs + (uint32_t)(nc * 16 * B_VRB + kt * 32);
                uint32_t vh4[4], vl4[4];
                LDSM4(vh4, a);
                LDSM4(vl4, a + B_VHL);
                MMA(O[2 * nc],     pah, vh4[0], vh4[2]);
                MMA(O[2 * nc + 1], pah, vh4[1], vh4[3]);
                MMA(O[2 * nc],     pah, vl4[0], vl4[2]);
                MMA(O[2 * nc + 1], pah, vl4[1], vl4[3]);
                MMA(O[2 * nc],     pal, vh4[0], vh4[2]);
                MMA(O[2 * nc + 1], pal, vh4[1], vh4[3]);
            }
        }
        __syncthreads();
    }

    // epilogue: divide by lsum, write [L][B][D]
    int r0 = qX * 128 + w * 16 + (lane >> 2);
    float inv0 = 1.f / g_lsum[b * LSEQ + r0];
    float inv1 = 1.f / g_lsum[b * LSEQ + r0 + 8];
    int cb = dh * 256 + (lane & 3) * 2;
#pragma unroll
    for (int nt = 0; nt < 32; nt++) {
        int col = cb + nt * 8;
        float2 o0 = make_float2(O[nt][0] * inv0, O[nt][1] * inv0);
        float2 o1 = make_float2(O[nt][2] * inv1, O[nt][3] * inv1);
        *(float2*)(out + ((size_t)r0 * BATCH + b) * DD + col) = o0;
        *(float2*)(out + ((size_t)(r0 + 8) * BATCH + b) * DD + col) = o1;
    }
}

// ---------------------------------------------------------------------------
extern "C" void kernel_launch(void* const* d_in, const int* in_sizes, int n_in,
                              void* d_out, int out_size)
{
    const float* query = (const float*)d_in[0];
    const float* key   = (const float*)d_in[1];
    const float* value = (const float*)d_in[2];
    const float* WKw   = (const float*)d_in[3];
    const float* WKb   = (const float*)d_in[4];
    const float* WVw   = (const float*)d_in[5];
    const float* WVb   = (const float*)d_in[6];
    float* out = (float*)d_out;
    (void)in_sizes; (void)n_in; (void)out_size;

    void *qh, *ql, *kh, *kl, *vh, *vl;
    cudaGetSymbolAddress(&qh, g_qh); cudaGetSymbolAddress(&ql, g_ql);
    cudaGetSymbolAddress(&kh, g_kh); cudaGetSymbolAddress(&kl, g_kl);
    cudaGetSymbolAddress(&vh, g_vh); cudaGetSymbolAddress(&vl, g_vl);

    cudaFuncSetAttribute(qk_kernel,
                         cudaFuncAttributeMaxDynamicSharedMemorySize, A_TOT);
    cudaFuncSetAttribute(pv_kernel,
                         cudaFuncAttributeMaxDynamicSharedMemorySize, B_TOT);

    dim3 gqk(LSEQ * BATCH / 16);
    proj_qk_kernel<<<gqk, 128>>>(query, WKw, WKb,
                                 (__nv_bfloat16*)qh, (__nv_bfloat16*)ql);
    proj_qk_kernel<<<gqk, 128>>>(key, WKw, WKb,
                                 (__nv_bfloat16*)kh, (__nv_bfloat16*)kl);
    dim3 gv(LSEQ * BATCH / 16, 4);
    proj_v_kernel<<<gv, 128>>>(value, WVw, WVb,
                               (__nv_bfloat16*)vh, (__nv_bfloat16*)vl);

    dim3 ga(LSEQ / 64, BATCH);
    qk_kernel<<<ga, 256, A_TOT>>>();
    dim3 gb(LSEQ / 128, BATCH, 2);
    pv_kernel<<<gb, 256, B_TOT>>>(out);
}